// round 6
// baseline (speedup 1.0000x reference)
#include <cuda_runtime.h>
#include <math.h>

// RT-DETR post-processing, three kernels:
//   K1 : per-query sigmoid-max/argmax, 8 queries/warp (REDUX-based) -> u64 keys
//   K2a: per (batch, half) bitonic sort of 512 keys, both halves DESC
//   K2b: bitonic halver (keep top 512) + short merge + emit top-300
// Output (concat f32): scores[256,300] | labels[256,300] | boxes[256,300,4]

#define NB      256
#define NQ      1000
#define NC      80
#define SORT_N  1024
#define TOPK    300
#define THRESH  0.05f
#define K1_QPW  8

typedef unsigned long long u64;
typedef unsigned int       u32;

__device__ u64 g_keys[NB * SORT_N];   // 2 MB scratch

__device__ __forceinline__ u32 f2ord(u32 b) {            // order-preserving f32->u32
    return (b & 0x80000000u) ? ~b : (b | 0x80000000u);
}
__device__ __forceinline__ u32 ord2f(u32 u) {
    return (u & 0x80000000u) ? (u ^ 0x80000000u) : ~u;
}

// ---------------------------------------------------------------------------
// K1: grid=4000, block=256 (8 warps); each warp handles 8 consecutive queries.
// ---------------------------------------------------------------------------
__global__ __launch_bounds__(256)
void k1_argmax(const float* __restrict__ logits)
{
    const int warp = threadIdx.x >> 5;
    const int lane = threadIdx.x & 31;
    const int f0   = (blockIdx.x * 8 + warp) * K1_QPW;   // first flat query

    const float4* base = (const float4*)logits + (size_t)f0 * (NC / 4);

    const bool act = lane < (NC / 4);          // 20 data lanes
    const int  ln  = act ? lane : 0;           // clamp addr (stay in bounds)

    float4 x[K1_QPW];
    #pragma unroll
    for (int j = 0; j < K1_QPW; j++)           // 8 independent LDG.128
        x[j] = base[j * (NC / 4) + ln];

    u32 m[K1_QPW], am[K1_QPW];
    #pragma unroll
    for (int j = 0; j < K1_QPW; j++) {
        float v = x[j].x; int idx = lane * 4;  // ties -> lowest class index
        if (x[j].y > v) { v = x[j].y; idx = lane * 4 + 1; }
        if (x[j].z > v) { v = x[j].z; idx = lane * 4 + 2; }
        if (x[j].w > v) { v = x[j].w; idx = lane * 4 + 3; }
        u32 u = act ? f2ord(__float_as_uint(v)) : 0u;   // inactive lanes lose
        m[j] = __reduce_max_sync(0xffffffffu, u);
        u32 cand = (u == m[j]) ? (u32)idx : 1023u;
        am[j] = __reduce_min_sync(0xffffffffu, cand);
    }

    if (lane < K1_QPW) {     // lane j finalizes query j (coalesced 64B store)
        u32 mm = m[0], aa = am[0];
        #pragma unroll
        for (int j = 1; j < K1_QPW; j++)
            if (lane == j) { mm = m[j]; aa = am[j]; }
        float v     = __uint_as_float(ord2f(mm));
        float score = 1.0f / (1.0f + expf(-v));
        float ms    = (score > THRESH) ? score : -1.0f;
        u32 sbits   = f2ord(__float_as_uint(ms));
        int f = f0 + lane;
        int b = f / NQ;
        int q = f - b * NQ;
        // [score 32b | (0xFFFF - q) 16b (ties -> lower q) | label 16b]
        g_keys[b * SORT_N + q] = ((u64)sbits << 32)
                               | ((u64)(u32)(0xFFFF - q) << 16)
                               | (u64)aa;
    }
}

// ---------------------------------------------------------------------------
// Bitonic helpers (descending only; hybrid register/shfl + smem)
// ---------------------------------------------------------------------------
__device__ __forceinline__ u64 keep_mm(u64 v, u64 pv, bool kmax) {
    return kmax ? (v > pv ? v : pv) : (v < pv ? v : pv);
}

template<int K, int JSTART>
__device__ __forceinline__ void reg_merge(u64 &v0, u64 &v1, int e0, int e1)
{
    #pragma unroll
    for (int j = JSTART; j >= 1; j >>= 1) {
        if (j == 32) {
            bool desc = ((e0 & K) == 0);
            if (desc ? (v0 < v1) : (v0 > v1)) { u64 t = v0; v0 = v1; v1 = t; }
        } else {
            u64 p0 = __shfl_xor_sync(0xffffffffu, v0, j);
            u64 p1 = __shfl_xor_sync(0xffffffffu, v1, j);
            bool desc0 = ((e0 & K) == 0);
            bool desc1 = ((e1 & K) == 0);
            bool low   = ((e0 & j) == 0);
            v0 = keep_mm(v0, p0, desc0 == low);
            v1 = keep_mm(v1, p1, desc1 == low);
        }
    }
}

__device__ __forceinline__ void smem_step(u64* keys, int t, int j, int k)
{
    int i  = ((t & ~(j - 1)) << 1) | (t & (j - 1));
    int ix = i + j;
    u64 a = keys[i];
    u64 c = keys[ix];
    bool desc = ((i & k) == 0);
    if (desc ? (a < c) : (a > c)) { keys[i] = c; keys[ix] = a; }
}

// ---------------------------------------------------------------------------
// K2a: grid=(2, 256), block=256. Sorts its 512 keys DESC (both halves).
// Thread t (warp w 0..7, lane l) owns local elements e0=64w+l, e1=e0+32.
// ---------------------------------------------------------------------------
__global__ __launch_bounds__(256)
void k2a_sort512()
{
    __shared__ u64 keys[512];

    const int h  = blockIdx.x;
    const int b  = blockIdx.y;
    const int t  = threadIdx.x;
    const int w  = t >> 5;
    const int l  = t & 31;
    const int e0 = 64 * w + l;
    const int e1 = e0 + 32;

    u64* gk = g_keys + (size_t)b * SORT_N + h * 512;

    int f0 = h * 512 + e0, f1 = h * 512 + e1;
    u64 v0 = (f0 < NQ) ? gk[e0] : 0ull;   // padding below all real keys
    u64 v1 = (f1 < NQ) ? gk[e1] : 0ull;

    reg_merge<2,  1 >(v0, v1, e0, e1);
    reg_merge<4,  2 >(v0, v1, e0, e1);
    reg_merge<8,  4 >(v0, v1, e0, e1);
    reg_merge<16, 8 >(v0, v1, e0, e1);
    reg_merge<32, 16>(v0, v1, e0, e1);
    reg_merge<64, 32>(v0, v1, e0, e1);
    keys[e0] = v0; keys[e1] = v1;
    __syncthreads();

    smem_step(keys, t, 64, 128);  __syncthreads();
    v0 = keys[e0]; v1 = keys[e1];
    reg_merge<128, 32>(v0, v1, e0, e1);
    keys[e0] = v0; keys[e1] = v1;
    __syncthreads();

    smem_step(keys, t, 128, 256); __syncthreads();
    smem_step(keys, t,  64, 256); __syncthreads();
    v0 = keys[e0]; v1 = keys[e1];
    reg_merge<256, 32>(v0, v1, e0, e1);
    keys[e0] = v0; keys[e1] = v1;
    __syncthreads();

    smem_step(keys, t, 256, 512); __syncthreads();
    smem_step(keys, t, 128, 512); __syncthreads();
    smem_step(keys, t,  64, 512); __syncthreads();
    v0 = keys[e0]; v1 = keys[e1];
    reg_merge<512, 32>(v0, v1, e0, e1);

    gk[e0] = v0; gk[e1] = v1;             // fully sorted descending
}

// ---------------------------------------------------------------------------
// K2b: grid=256, block=256. Halver keeps top 512 (bitonic), merge, emit 300.
// ---------------------------------------------------------------------------
__device__ __forceinline__ void emit_one(u64 key, int e, int b,
                                         float img_w, float img_h,
                                         const float* __restrict__ boxes,
                                         float* __restrict__ out)
{
    const int S = NB * TOPK;
    u32 u    = (u32)(key >> 32);
    float ms = __uint_as_float(ord2f(u));
    int q    = 0xFFFF - (int)((key >> 16) & 0xFFFFu);
    int lab  = (int)(key & 0xFFFFu);
    bool valid = ms > THRESH;

    int o = b * TOPK + e;
    out[o]     = valid ? ms : 0.0f;
    out[S + o] = valid ? (float)lab : -1.0f;

    float4 bx = ((const float4*)boxes)[(size_t)b * NQ + q];
    float x0 = (bx.x - 0.5f * bx.z) * img_w;
    float y0 = (bx.y - 0.5f * bx.w) * img_h;
    float x1 = (bx.x + 0.5f * bx.z) * img_w;
    float y1 = (bx.y + 0.5f * bx.w) * img_h;
    ((float4*)(out + 2 * S))[o] = valid ? make_float4(x0, y0, x1, y1)
                                        : make_float4(0.f, 0.f, 0.f, 0.f);
}

__global__ __launch_bounds__(256)
void k2b_merge_emit(const float* __restrict__ boxes,
                    const float* __restrict__ tsizes,
                    float* __restrict__ out)
{
    __shared__ u64 keys[512];

    const int b = blockIdx.x;
    const int t = threadIdx.x;
    const int w = t >> 5;
    const int l = t & 31;
    const int e0 = 64 * w + l;     // 0..511
    const int e1 = e0 + 32;

    const u64* gk = g_keys + (size_t)b * SORT_N;

    // Halver: both halves sorted DESC; C[i] = max(A[i], B[511-i]) holds the
    // 512 largest keys and is bitonic. Bottom half never touched again.
    {
        u64 a0 = gk[t];         u64 b0 = gk[1023 - t];
        u64 a1 = gk[t + 256];   u64 b1 = gk[767  - t];
        keys[t]       = (a0 > b0) ? a0 : b0;
        keys[t + 256] = (a1 > b1) ? a1 : b1;
    }
    __syncthreads();

    // Bitonic merge of 512, descending (k=512 => all desc)
    smem_step(keys, t, 256, 512); __syncthreads();
    smem_step(keys, t, 128, 512); __syncthreads();
    smem_step(keys, t,  64, 512); __syncthreads();

    u64 v0 = keys[e0], v1 = keys[e1];
    reg_merge<1024, 32>(v0, v1, e0, e1);   // K>511 => all desc

    const float img_h = tsizes[2 * b + 0];
    const float img_w = tsizes[2 * b + 1];
    if (e0 < TOPK) emit_one(v0, e0, b, img_w, img_h, boxes, out);
    if (e1 < TOPK) emit_one(v1, e1, b, img_w, img_h, boxes, out);
}

// ---------------------------------------------------------------------------
extern "C" void kernel_launch(void* const* d_in, const int* in_sizes, int n_in,
                              void* d_out, int out_size)
{
    const float* logits = (const float*)d_in[0];   // (256,1000,80) f32
    const float* boxes  = (const float*)d_in[1];   // (256,1000,4)  f32
    const float* tsizes = (const float*)d_in[2];   // (256,2)       f32
    float* out = (float*)d_out;                    // 460800 f32

    k1_argmax<<<4000, 256>>>(logits);
    k2a_sort512<<<dim3(2, NB), 256>>>();
    k2b_merge_emit<<<NB, 256>>>(boxes, tsizes, out);
}

// round 7
// speedup vs baseline: 1.2193x; 1.2193x over previous
#include <cuda_runtime.h>
#include <math.h>

// RT-DETR post-processing, three kernels:
//   K1 : per-query sigmoid-max/argmax (REDUX-based, 4 queries/warp) -> u64 keys
//   K2a: per (batch, half) bitonic sort of 512 keys, both halves DESC
//   K2b: bitonic halver (keep top 512) + short merge + emit top-300
// Output (concat f32): scores[256,300] | labels[256,300] | boxes[256,300,4]

#define NB      256
#define NQ      1000
#define NC      80
#define SORT_N  1024
#define TOPK    300
#define THRESH  0.05f

typedef unsigned long long u64;
typedef unsigned int       u32;

__device__ u64 g_keys[NB * SORT_N];   // 2 MB scratch

__device__ __forceinline__ u32 f2ord(u32 b) {            // order-preserving f32->u32
    return (b & 0x80000000u) ? ~b : (b | 0x80000000u);
}
__device__ __forceinline__ u32 ord2f(u32 u) {
    return (u & 0x80000000u) ? (u ^ 0x80000000u) : ~u;
}

// ---------------------------------------------------------------------------
// K1: grid=8000, block=256 (8 warps); each warp handles 4 consecutive queries.
// (R5 shape: load->reduce interleaved, low regs, high occupancy.)
// ---------------------------------------------------------------------------
__global__ __launch_bounds__(256)
void k1_argmax(const float* __restrict__ logits)
{
    const int warp = threadIdx.x >> 5;
    const int lane = threadIdx.x & 31;
    const int f0   = (blockIdx.x * 8 + warp) * 4;     // first flat query (b*NQ+q)

    const float4* base = (const float4*)logits + (size_t)f0 * (NC / 4);

    u32 u[4]; int id[4];
    #pragma unroll
    for (int j = 0; j < 4; j++) { u[j] = 0u; id[j] = 1023; }

    if (lane < NC / 4) {                              // 20 lanes carry data
        #pragma unroll
        for (int j = 0; j < 4; j++) {                 // 4 independent LDG.128
            float4 x = base[j * (NC / 4) + lane];
            float v = x.x; int idx = lane * 4;
            if (x.y > v) { v = x.y; idx = lane * 4 + 1; }
            if (x.z > v) { v = x.z; idx = lane * 4 + 2; }
            if (x.w > v) { v = x.w; idx = lane * 4 + 3; }
            u[j]  = f2ord(__float_as_uint(v));
            id[j] = idx;
        }
    }

    u32 m[4], am[4];
    #pragma unroll
    for (int j = 0; j < 4; j++) {
        m[j] = __reduce_max_sync(0xffffffffu, u[j]);
        u32 cand = (u[j] == m[j]) ? (u32)id[j] : 1023u;   // ties -> lowest class
        am[j] = __reduce_min_sync(0xffffffffu, cand);
    }

    if (lane < 4) {   // lanes 0..3 finalize one query each (coalesced 32B store)
        u32 mm = (lane == 0) ? m[0]  : (lane == 1) ? m[1]  : (lane == 2) ? m[2]  : m[3];
        u32 aa = (lane == 0) ? am[0] : (lane == 1) ? am[1] : (lane == 2) ? am[2] : am[3];
        float v     = __uint_as_float(ord2f(mm));
        float score = 1.0f / (1.0f + expf(-v));
        float ms    = (score > THRESH) ? score : -1.0f;
        u32 sbits   = f2ord(__float_as_uint(ms));
        int f = f0 + lane;
        int b = f / NQ;
        int q = f - b * NQ;
        // [score 32b | (0xFFFF - q) 16b (ties -> lower q) | label 16b]
        g_keys[b * SORT_N + q] = ((u64)sbits << 32)
                               | ((u64)(u32)(0xFFFF - q) << 16)
                               | (u64)aa;
    }
}

// ---------------------------------------------------------------------------
// Bitonic helpers (descending only; hybrid register/shfl + smem)
// ---------------------------------------------------------------------------
__device__ __forceinline__ u64 keep_mm(u64 v, u64 pv, bool kmax) {
    return kmax ? (v > pv ? v : pv) : (v < pv ? v : pv);
}

template<int K, int JSTART>
__device__ __forceinline__ void reg_merge(u64 &v0, u64 &v1, int e0, int e1)
{
    #pragma unroll
    for (int j = JSTART; j >= 1; j >>= 1) {
        if (j == 32) {
            bool desc = ((e0 & K) == 0);
            if (desc ? (v0 < v1) : (v0 > v1)) { u64 t = v0; v0 = v1; v1 = t; }
        } else {
            u64 p0 = __shfl_xor_sync(0xffffffffu, v0, j);
            u64 p1 = __shfl_xor_sync(0xffffffffu, v1, j);
            bool desc0 = ((e0 & K) == 0);
            bool desc1 = ((e1 & K) == 0);
            bool low   = ((e0 & j) == 0);
            v0 = keep_mm(v0, p0, desc0 == low);
            v1 = keep_mm(v1, p1, desc1 == low);
        }
    }
}

__device__ __forceinline__ void smem_step(u64* keys, int t, int j, int k)
{
    int i  = ((t & ~(j - 1)) << 1) | (t & (j - 1));
    int ix = i + j;
    u64 a = keys[i];
    u64 c = keys[ix];
    bool desc = ((i & k) == 0);
    if (desc ? (a < c) : (a > c)) { keys[i] = c; keys[ix] = a; }
}

// ---------------------------------------------------------------------------
// K2a: grid=(2, 256), block=256. Sorts its 512 keys DESC (both halves).
// Thread t (warp w 0..7, lane l) owns local elements e0=64w+l, e1=e0+32.
// ---------------------------------------------------------------------------
__global__ __launch_bounds__(256)
void k2a_sort512()
{
    __shared__ u64 keys[512];

    const int h  = blockIdx.x;
    const int b  = blockIdx.y;
    const int t  = threadIdx.x;
    const int w  = t >> 5;
    const int l  = t & 31;
    const int e0 = 64 * w + l;
    const int e1 = e0 + 32;

    u64* gk = g_keys + (size_t)b * SORT_N + h * 512;

    int f0 = h * 512 + e0, f1 = h * 512 + e1;
    u64 v0 = (f0 < NQ) ? gk[e0] : 0ull;   // padding below all real keys
    u64 v1 = (f1 < NQ) ? gk[e1] : 0ull;

    reg_merge<2,  1 >(v0, v1, e0, e1);
    reg_merge<4,  2 >(v0, v1, e0, e1);
    reg_merge<8,  4 >(v0, v1, e0, e1);
    reg_merge<16, 8 >(v0, v1, e0, e1);
    reg_merge<32, 16>(v0, v1, e0, e1);
    reg_merge<64, 32>(v0, v1, e0, e1);
    keys[e0] = v0; keys[e1] = v1;
    __syncthreads();

    smem_step(keys, t, 64, 128);  __syncthreads();
    v0 = keys[e0]; v1 = keys[e1];
    reg_merge<128, 32>(v0, v1, e0, e1);
    keys[e0] = v0; keys[e1] = v1;
    __syncthreads();

    smem_step(keys, t, 128, 256); __syncthreads();
    smem_step(keys, t,  64, 256); __syncthreads();
    v0 = keys[e0]; v1 = keys[e1];
    reg_merge<256, 32>(v0, v1, e0, e1);
    keys[e0] = v0; keys[e1] = v1;
    __syncthreads();

    smem_step(keys, t, 256, 512); __syncthreads();
    smem_step(keys, t, 128, 512); __syncthreads();
    smem_step(keys, t,  64, 512); __syncthreads();
    v0 = keys[e0]; v1 = keys[e1];
    reg_merge<512, 32>(v0, v1, e0, e1);

    gk[e0] = v0; gk[e1] = v1;             // fully sorted descending
}

// ---------------------------------------------------------------------------
// K2b: grid=256, block=256. Halver keeps top 512 (bitonic), merge, emit 300.
// ---------------------------------------------------------------------------
__device__ __forceinline__ void emit_one(u64 key, int e, int b,
                                         float img_w, float img_h,
                                         const float* __restrict__ boxes,
                                         float* __restrict__ out)
{
    const int S = NB * TOPK;
    u32 u    = (u32)(key >> 32);
    float ms = __uint_as_float(ord2f(u));
    int q    = 0xFFFF - (int)((key >> 16) & 0xFFFFu);
    int lab  = (int)(key & 0xFFFFu);
    bool valid = ms > THRESH;

    int o = b * TOPK + e;
    out[o]     = valid ? ms : 0.0f;
    out[S + o] = valid ? (float)lab : -1.0f;

    float4 bx = ((const float4*)boxes)[(size_t)b * NQ + q];
    float x0 = (bx.x - 0.5f * bx.z) * img_w;
    float y0 = (bx.y - 0.5f * bx.w) * img_h;
    float x1 = (bx.x + 0.5f * bx.z) * img_w;
    float y1 = (bx.y + 0.5f * bx.w) * img_h;
    ((float4*)(out + 2 * S))[o] = valid ? make_float4(x0, y0, x1, y1)
                                        : make_float4(0.f, 0.f, 0.f, 0.f);
}

__global__ __launch_bounds__(256)
void k2b_merge_emit(const float* __restrict__ boxes,
                    const float* __restrict__ tsizes,
                    float* __restrict__ out)
{
    __shared__ u64 keys[512];

    const int b = blockIdx.x;
    const int t = threadIdx.x;
    const int w = t >> 5;
    const int l = t & 31;
    const int e0 = 64 * w + l;     // 0..511
    const int e1 = e0 + 32;

    const u64* gk = g_keys + (size_t)b * SORT_N;

    // Halver: both halves sorted DESC; C[i] = max(A[i], B[511-i]) holds the
    // 512 largest keys and is bitonic. Bottom half never touched again.
    {
        u64 a0 = gk[t];         u64 b0 = gk[1023 - t];
        u64 a1 = gk[t + 256];   u64 b1 = gk[767  - t];
        keys[t]       = (a0 > b0) ? a0 : b0;
        keys[t + 256] = (a1 > b1) ? a1 : b1;
    }
    __syncthreads();

    // Bitonic merge of 512, descending (k=512 => all desc)
    smem_step(keys, t, 256, 512); __syncthreads();
    smem_step(keys, t, 128, 512); __syncthreads();
    smem_step(keys, t,  64, 512); __syncthreads();

    u64 v0 = keys[e0], v1 = keys[e1];
    reg_merge<1024, 32>(v0, v1, e0, e1);   // K>511 => all desc

    const float img_h = tsizes[2 * b + 0];
    const float img_w = tsizes[2 * b + 1];
    if (e0 < TOPK) emit_one(v0, e0, b, img_w, img_h, boxes, out);
    if (e1 < TOPK) emit_one(v1, e1, b, img_w, img_h, boxes, out);
}

// ---------------------------------------------------------------------------
extern "C" void kernel_launch(void* const* d_in, const int* in_sizes, int n_in,
                              void* d_out, int out_size)
{
    const float* logits = (const float*)d_in[0];   // (256,1000,80) f32
    const float* boxes  = (const float*)d_in[1];   // (256,1000,4)  f32
    const float* tsizes = (const float*)d_in[2];   // (256,2)       f32
    float* out = (float*)d_out;                    // 460800 f32

    k1_argmax<<<8000, 256>>>(logits);
    k2a_sort512<<<dim3(2, NB), 256>>>();
    k2b_merge_emit<<<NB, 256>>>(boxes, tsizes, out);
}